// round 14
// baseline (speedup 1.0000x reference)
#include <cuda_runtime.h>
#include <cuda_fp16.h>
#include <cstdint>
#include <math.h>

#define Bb 4
#define Ss 1024
#define Dd 1024
#define Ee 8
#define DEe 128
#define SCALEF 0.03125f

// ---------------- scratch ----------------
__device__ __half g_scores[(size_t)Ee * Bb * Ss * Ss];  // exp(score*scale), fp16
__device__ float g_psum[(size_t)Ee * Bb * 8 * Ss];      // per (pair, t-tile) row sums (fp32, exact)
__device__ float g_attn[(size_t)Bb * Ss * Ss];          // tf32-rounded normalized probs
__device__ float g_vt[(size_t)Bb * 2 * DEe * Ss];       // tf32-rounded transposed V [b][se][d][t]

__device__ __forceinline__ uint32_t f2tf(float x) {
    uint32_t u;
    asm("cvt.rna.tf32.f32 %0, %1;" : "=r"(u) : "f"(x));
    return u;
}

__device__ __forceinline__ void mma_tf32(float* d, const uint32_t* a, const uint32_t* b) {
    asm volatile(
        "mma.sync.aligned.m16n8k8.row.col.f32.tf32.tf32.f32 "
        "{%0,%1,%2,%3}, {%4,%5,%6,%7}, {%8,%9}, {%0,%1,%2,%3};"
        : "+f"(d[0]), "+f"(d[1]), "+f"(d[2]), "+f"(d[3])
        : "r"(a[0]), "r"(a[1]), "r"(a[2]), "r"(a[3]), "r"(b[0]), "r"(b[1]));
}

__device__ __forceinline__ void cp16(uint32_t* sdst, const float* gsrc) {
    uint32_t sa = (uint32_t)__cvta_generic_to_shared(sdst);
    asm volatile("cp.async.cg.shared.global [%0], [%1], 16;" :: "r"(sa), "l"(gsrc));
}
#define CP_COMMIT() asm volatile("cp.async.commit_group;" ::: "memory")
#define CP_WAIT1()  asm volatile("cp.async.wait_group 1;" ::: "memory")
#define CP_WAIT2()  asm volatile("cp.async.wait_group 2;" ::: "memory")

// ====================== Kernel 1: QK^T, cp.async 3-stage, fused exp + psum ======================
#define QCH 32
#define QSTR 36
#define QSTAGE (2 * 128 * QSTR)            // u32 per stage (A tile + B tile)
#define QK_SMEM (3 * QSTAGE * 4 + 512)     // 3 stages + ps[128]

__device__ __forceinline__ void qk_issue(const float* Ag, const float* Bg, int kc,
                                         uint32_t* stage, int tid) {
    uint32_t* As = stage;
    uint32_t* Bs = stage + 128 * QSTR;
    int row = tid >> 3, col = (tid & 7) << 2;
#pragma unroll
    for (int i = 0; i < 4; i++) {
        int r = row + 32 * i;
        cp16(&As[r * QSTR + col], Ag + (size_t)r * Dd + kc * QCH + col);
        cp16(&Bs[r * QSTR + col], Bg + (size_t)r * Dd + kc * QCH + col);
    }
}

__global__ void __launch_bounds__(256) qk_mma(const float* __restrict__ Q,
                                              const float* __restrict__ K,
                                              const int* __restrict__ emask) {
    int pair = blockIdx.z;              // e*4 + b
    if (emask[pair] == 0) return;
    int e = pair >> 2, b = pair & 3;
    int t0 = blockIdx.x << 7;
    int s0 = blockIdx.y << 7;

    extern __shared__ uint32_t sh[];
    uint32_t* stg[3] = { sh, sh + QSTAGE, sh + 2 * QSTAGE };
    float* ps = (float*)(sh + 3 * QSTAGE);

    int tid = threadIdx.x;
    int wid = tid >> 5, lane = tid & 31;
    int wm = wid & 1, wn = wid >> 1;    // warps: 2 (m) x 4 (n)
    int gq = lane >> 2, c = lane & 3;

    if (tid < 128) ps[tid] = 0.f;

    const float* Ag = Q + (size_t)(b * Ss + s0) * Dd + e * DEe;
    const float* Bg = K + (size_t)(b * Ss + t0) * Dd + e * DEe;

    float acc[4][4][4] = {};

    qk_issue(Ag, Bg, 0, stg[0], tid); CP_COMMIT();
    qk_issue(Ag, Bg, 1, stg[1], tid); CP_COMMIT();

#pragma unroll 1
    for (int kc = 0; kc < 4; kc++) {
        if (kc + 2 < 4) qk_issue(Ag, Bg, kc + 2, stg[(kc + 2) % 3], tid);
        CP_COMMIT();                    // real or empty group: keeps pending count fixed
        CP_WAIT2();
        __syncthreads();
        const uint32_t* As = stg[kc % 3];
        const uint32_t* Bs = As + 128 * QSTR;
#pragma unroll
        for (int ks = 0; ks < 4; ks++) {
            int k0 = ks * 8;
            uint32_t af[4][4], bf[4][2];
#pragma unroll
            for (int mt = 0; mt < 4; mt++) {
                int r0 = wm * 64 + mt * 16;
                af[mt][0] = As[(r0 + gq) * QSTR + k0 + c];
                af[mt][1] = As[(r0 + gq + 8) * QSTR + k0 + c];
                af[mt][2] = As[(r0 + gq) * QSTR + k0 + c + 4];
                af[mt][3] = As[(r0 + gq + 8) * QSTR + k0 + c + 4];
            }
#pragma unroll
            for (int nt = 0; nt < 4; nt++) {
                int n0 = wn * 32 + nt * 8;
                bf[nt][0] = Bs[(n0 + gq) * QSTR + k0 + c];
                bf[nt][1] = Bs[(n0 + gq) * QSTR + k0 + c + 4];
            }
#pragma unroll
            for (int mt = 0; mt < 4; mt++)
#pragma unroll
                for (int nt = 0; nt < 4; nt++)
                    mma_tf32(acc[mt][nt], af[mt], bf[nt]);
        }
        __syncthreads();
    }

    // Epilogue: exp (fp32) -> fp16 store + exact fp32 row-sum partials
    __half* outbase = g_scores + (size_t)pair * Ss * Ss;
#pragma unroll
    for (int mt = 0; mt < 4; mt++) {
        int rl = wm * 64 + mt * 16 + gq;
        float slo = 0.f, shi = 0.f;
#pragma unroll
        for (int nt = 0; nt < 4; nt++) {
            int colg = t0 + wn * 32 + nt * 8 + 2 * c;
            float e0 = __expf(acc[mt][nt][0] * SCALEF);
            float e1 = __expf(acc[mt][nt][1] * SCALEF);
            float e2 = __expf(acc[mt][nt][2] * SCALEF);
            float e3 = __expf(acc[mt][nt][3] * SCALEF);
            *(__half2*)(outbase + (size_t)(s0 + rl) * Ss + colg)     = __floats2half2_rn(e0, e1);
            *(__half2*)(outbase + (size_t)(s0 + rl + 8) * Ss + colg) = __floats2half2_rn(e2, e3);
            slo += e0 + e1; shi += e2 + e3;
        }
        slo += __shfl_xor_sync(0xFFFFFFFF, slo, 1);
        slo += __shfl_xor_sync(0xFFFFFFFF, slo, 2);
        shi += __shfl_xor_sync(0xFFFFFFFF, shi, 1);
        shi += __shfl_xor_sync(0xFFFFFFFF, shi, 2);
        if (c == 0) {
            atomicAdd(&ps[rl], slo);
            atomicAdd(&ps[rl + 8], shi);
        }
    }
    __syncthreads();
    if (tid < 128)
        g_psum[((size_t)pair * 8 + blockIdx.x) * Ss + s0 + tid] = ps[tid];
}

// ---------------- top-2 (ties -> lower index, matches jax top_k) ----------------
__device__ __forceinline__ void top2(const float* __restrict__ rp, int b, int& bi, int& si) {
    float best = -1e30f, second = -1e30f;
    bi = -1; si = -1;
#pragma unroll
    for (int e = 0; e < Ee; e++) {
        float v = rp[b * Ee + e];
        if (v > best)        { second = best; si = bi; best = v; bi = e; }
        else if (v > second) { second = v; si = e; }
    }
}

// ====================== Kernel 2: combine (fp16 in, tf32 fp32 out) + zero-fill out slices ======================
__global__ void __launch_bounds__(256) combine_kernel(const int* __restrict__ emask,
                                                      const float* __restrict__ rp,
                                                      float* __restrict__ outG) {
    int row = blockIdx.x;               // b*1024 + s
    int b = row >> 10, s = row & 1023;
    int tid = threadIdx.x;

    float4 a = make_float4(0.f, 0.f, 0.f, 0.f);
    for (int e = 0; e < Ee; e++) {
        int pair = e * Bb + b;
        if (emask[pair] == 0) continue;
        float sm = 0.f;
#pragma unroll
        for (int nt = 0; nt < 8; nt++)
            sm += g_psum[((size_t)pair * 8 + nt) * Ss + s];
        float inv = 1.0f / sm;
        uint2 raw = *(const uint2*)(g_scores + ((size_t)pair * Ss + s) * Ss + tid * 4);
        float2 f0 = __half22float2(*reinterpret_cast<__half2*>(&raw.x));
        float2 f1 = __half22float2(*reinterpret_cast<__half2*>(&raw.y));
        a.x += f0.x * inv; a.y += f0.y * inv;
        a.z += f1.x * inv; a.w += f1.y * inv;
    }
    uint4 o;
    o.x = f2tf(a.x); o.y = f2tf(a.y); o.z = f2tf(a.z); o.w = f2tf(a.w);
    *(uint4*)(g_attn + (size_t)row * Ss + tid * 4) = o;

    // zero the 6 non-selected 128-wide output slices of this (b, s) row
    int bi, si; top2(rp, b, bi, si);
    if (tid < 192) {
        int sl = tid >> 5;              // 0..5
        int cc = (tid & 31) << 2;       // float offset in slice
        int e, cnt = 0, eSel = -1;
#pragma unroll
        for (e = 0; e < Ee; e++) {
            if (e == bi || e == si) continue;
            if (cnt == sl) { eSel = e; }
            cnt++;
        }
        *(float4*)(outG + (size_t)row * Dd + eSel * DEe + cc) =
            make_float4(0.f, 0.f, 0.f, 0.f);
    }
}

// ====================== Kernel 3: transpose selected V slices (tf32-rounded) ======================
__global__ void __launch_bounds__(256) vt_prep(const float* __restrict__ V,
                                               const float* __restrict__ rp) {
    int tt = blockIdx.x;
    int se = blockIdx.y;
    int b  = blockIdx.z;
    int bi, si; top2(rp, b, bi, si);
    int eSel = (se == 0) ? bi : si;

    __shared__ float tile[64][132];
    int tid = threadIdx.x;
#pragma unroll
    for (int i = 0; i < 8; i++) {
        int v = tid + 256 * i;
        int r = v >> 5;
        int c = (v & 31) << 2;
        float4 val = *(const float4*)(V + ((size_t)(b * Ss + tt * 64 + r)) * Dd + eSel * DEe + c);
        *(float4*)&tile[r][c] = val;
    }
    __syncthreads();
#pragma unroll
    for (int i = 0; i < 8; i++) {
        int v = tid + 256 * i;
        int d = v >> 4;
        int t4 = (v & 15) << 2;
        uint4 o;
        o.x = f2tf(tile[t4][d]);     o.y = f2tf(tile[t4 + 1][d]);
        o.z = f2tf(tile[t4 + 2][d]); o.w = f2tf(tile[t4 + 3][d]);
        *(uint4*)(g_vt + ((size_t)((b * 2 + se) * DEe + d)) * Ss + tt * 64 + t4) = o;
    }
}

// ====================== Kernel 4: out = attn @ V — M=32 tiles, 2-stage, 2 CTAs/SM ======================
#define AK 64
#define ASTR 68
#define STAGE_U32 ((32 + 128) * ASTR)      // 32 A rows + 128 B rows per stage
#define AV_SMEM (2 * STAGE_U32 * 4)        // 87 KB -> 2 CTAs/SM

__device__ __forceinline__ void av_issue(const float* Ag, const float* Bg, int kc,
                                         uint32_t* stage, int tid) {
    uint32_t* Abuf = stage;
    uint32_t* Bbuf = stage + 32 * ASTR;
#pragma unroll
    for (int i = 0; i < 2; i++) {       // A: 32 rows x 16 float4 = 512 slots
        int idx = tid + 256 * i;
        int row = idx >> 4;
        int col = (idx & 15) << 2;
        cp16(&Abuf[row * ASTR + col], Ag + (size_t)row * Ss + kc * AK + col);
    }
#pragma unroll
    for (int i = 0; i < 8; i++) {       // B: 128 rows x 16 float4 = 2048 slots
        int idx = tid + 256 * i;
        int row = idx >> 4;
        int col = (idx & 15) << 2;
        cp16(&Bbuf[row * ASTR + col], Bg + (size_t)row * Ss + kc * AK + col);
    }
}

__global__ void __launch_bounds__(256) av_mma(const float* __restrict__ rp,
                                              float* __restrict__ outG) {
    int st = blockIdx.x;                // 0..31 (32 rows each)
    int se = blockIdx.y;                // 0..1 selected expert
    int b  = blockIdx.z;
    int tid = threadIdx.x;
    int wid = tid >> 5, lane = tid & 31;
    int s0 = st << 5;

    int bi, si; top2(rp, b, bi, si);
    int e = (se == 0) ? bi : si;

    extern __shared__ uint32_t sh[];
    uint32_t* stg[2] = { sh, sh + STAGE_U32 };

    int wm = wid & 1, wn = wid >> 1;    // 2 (m, 16 rows) x 4 (n, 32 cols)
    int gq = lane >> 2, c = lane & 3;

    const float* Ag = g_attn + (size_t)(b * Ss + s0) * Ss;
    const float* Bg = g_vt + (size_t)(b * 2 + se) * DEe * Ss;

    float acc[4][4] = {};

    av_issue(Ag, Bg, 0, stg[0], tid); CP_COMMIT();

#pragma unroll 1
    for (int kc = 0; kc < 16; kc++) {
        if (kc + 1 < 16) av_issue(Ag, Bg, kc + 1, stg[(kc + 1) & 1], tid);
        CP_COMMIT();                    // real or empty: pending stays 2
        CP_WAIT1();                     // stage kc drained
        __syncthreads();
        const uint32_t* As = stg[kc & 1];
        const uint32_t* Bs = As + 32 * ASTR;
#pragma unroll
        for (int ks = 0; ks < 8; ks++) {
            int k0 = ks * 8;
            uint32_t af[4], bf[4][2];
            int r0 = wm * 16;
            af[0] = As[(r0 + gq) * ASTR + k0 + c];
            af[1] = As[(r0 + gq + 8) * ASTR + k0 + c];
            af[2] = As[(r0 + gq) * ASTR + k0 + c + 4];
            af[3] = As[(r0 + gq + 8) * ASTR + k0 + c + 4];
#pragma unroll
            for (int nt = 0; nt < 4; nt++) {
                int n0 = wn * 32 + nt * 8;
                bf[nt][0] = Bs[(n0 + gq) * ASTR + k0 + c];
                bf[nt][1] = Bs[(n0 + gq) * ASTR + k0 + c + 4];
            }
#pragma unroll
            for (int nt = 0; nt < 4; nt++)
                mma_tf32(acc[nt], af, bf[nt]);
        }
        __syncthreads();
    }

    int rl = wm * 16 + gq;
#pragma unroll
    for (int nt = 0; nt < 4; nt++) {
        int colg = e * DEe + wn * 32 + nt * 8 + 2 * c;
        *(float2*)(outG + ((size_t)(b * Ss + s0 + rl)) * Dd + colg) =
            make_float2(acc[nt][0], acc[nt][1]);
        *(float2*)(outG + ((size_t)(b * Ss + s0 + rl + 8)) * Dd + colg) =
            make_float2(acc[nt][2], acc[nt][3]);
    }
}

// ---------------- launch ----------------
extern "C" void kernel_launch(void* const* d_in, const int* in_sizes, int n_in,
                              void* d_out, int out_size) {
    const float* Q     = (const float*)d_in[0];
    const float* K     = (const float*)d_in[1];
    const float* V     = (const float*)d_in[2];
    const float* rp    = (const float*)d_in[3];
    const int*   emask = (const int*)  d_in[4];
    float* out = (float*)d_out;

    cudaFuncSetAttribute(qk_mma, cudaFuncAttributeMaxDynamicSharedMemorySize, QK_SMEM);
    cudaFuncSetAttribute(av_mma, cudaFuncAttributeMaxDynamicSharedMemorySize, AV_SMEM);

    vt_prep<<<dim3(16, 2, Bb), 256>>>(V, rp);
    qk_mma<<<dim3(8, 8, Ee * Bb), 256, QK_SMEM>>>(Q, K, emask);
    combine_kernel<<<Bb * Ss, 256>>>(emask, rp, out);
    av_mma<<<dim3(32, 2, Bb), 256, AV_SMEM>>>(rp, out);
}

// round 15
// speedup vs baseline: 1.2442x; 1.2442x over previous
#include <cuda_runtime.h>
#include <cuda_fp16.h>
#include <cstdint>
#include <math.h>

#define Bb 4
#define Ss 1024
#define Dd 1024
#define Ee 8
#define DEe 128
#define SCALEF 0.03125f

// ---------------- scratch ----------------
__device__ __half g_scores[(size_t)Ee * Bb * Ss * Ss];  // exp(score*scale), fp16
__device__ float g_psum[(size_t)Ee * Bb * 8 * Ss];      // per (pair, t-tile) row sums (fp32, exact)
__device__ __half g_attn[(size_t)Bb * Ss * Ss];         // fp16 normalized probs
__device__ __half g_vt[(size_t)Bb * 2 * DEe * Ss];      // fp16 transposed V [b][se][d][t]

__device__ __forceinline__ uint32_t f2tf(float x) {
    uint32_t u;
    asm("cvt.rna.tf32.f32 %0, %1;" : "=r"(u) : "f"(x));
    return u;
}

__device__ __forceinline__ void mma_tf32(float* d, const uint32_t* a, const uint32_t* b) {
    asm volatile(
        "mma.sync.aligned.m16n8k8.row.col.f32.tf32.tf32.f32 "
        "{%0,%1,%2,%3}, {%4,%5,%6,%7}, {%8,%9}, {%0,%1,%2,%3};"
        : "+f"(d[0]), "+f"(d[1]), "+f"(d[2]), "+f"(d[3])
        : "r"(a[0]), "r"(a[1]), "r"(a[2]), "r"(a[3]), "r"(b[0]), "r"(b[1]));
}

__device__ __forceinline__ void mma_f16(float* d, const uint32_t* a, const uint32_t* b) {
    asm volatile(
        "mma.sync.aligned.m16n8k16.row.col.f32.f16.f16.f32 "
        "{%0,%1,%2,%3}, {%4,%5,%6,%7}, {%8,%9}, {%0,%1,%2,%3};"
        : "+f"(d[0]), "+f"(d[1]), "+f"(d[2]), "+f"(d[3])
        : "r"(a[0]), "r"(a[1]), "r"(a[2]), "r"(a[3]), "r"(b[0]), "r"(b[1]));
}

__device__ __forceinline__ void cp16(void* sdst, const void* gsrc) {
    uint32_t sa = (uint32_t)__cvta_generic_to_shared(sdst);
    asm volatile("cp.async.cg.shared.global [%0], [%1], 16;" :: "r"(sa), "l"(gsrc));
}
#define CP_COMMIT() asm volatile("cp.async.commit_group;" ::: "memory")
#define CP_WAIT2()  asm volatile("cp.async.wait_group 2;" ::: "memory")

// ====================== Kernel 1: QK^T, cp.async 3-stage, fused exp + psum ======================
#define QCH 32
#define QSTR 36
#define QSTAGE (2 * 128 * QSTR)            // u32 per stage (A tile + B tile)
#define QK_SMEM (3 * QSTAGE * 4 + 512)     // 3 stages + ps[128]

__device__ __forceinline__ void qk_issue(const float* Ag, const float* Bg, int kc,
                                         uint32_t* stage, int tid) {
    uint32_t* As = stage;
    uint32_t* Bs = stage + 128 * QSTR;
    int row = tid >> 3, col = (tid & 7) << 2;
#pragma unroll
    for (int i = 0; i < 4; i++) {
        int r = row + 32 * i;
        cp16(&As[r * QSTR + col], Ag + (size_t)r * Dd + kc * QCH + col);
        cp16(&Bs[r * QSTR + col], Bg + (size_t)r * Dd + kc * QCH + col);
    }
}

__global__ void __launch_bounds__(256) qk_mma(const float* __restrict__ Q,
                                              const float* __restrict__ K,
                                              const int* __restrict__ emask) {
    int pair = blockIdx.z;              // e*4 + b
    if (emask[pair] == 0) return;
    int e = pair >> 2, b = pair & 3;
    int t0 = blockIdx.x << 7;
    int s0 = blockIdx.y << 7;

    extern __shared__ uint32_t sh[];
    uint32_t* stg[3] = { sh, sh + QSTAGE, sh + 2 * QSTAGE };
    float* ps = (float*)(sh + 3 * QSTAGE);

    int tid = threadIdx.x;
    int wid = tid >> 5, lane = tid & 31;
    int wm = wid & 1, wn = wid >> 1;    // warps: 2 (m) x 4 (n)
    int gq = lane >> 2, c = lane & 3;

    if (tid < 128) ps[tid] = 0.f;

    const float* Ag = Q + (size_t)(b * Ss + s0) * Dd + e * DEe;
    const float* Bg = K + (size_t)(b * Ss + t0) * Dd + e * DEe;

    float acc[4][4][4] = {};

    qk_issue(Ag, Bg, 0, stg[0], tid); CP_COMMIT();
    qk_issue(Ag, Bg, 1, stg[1], tid); CP_COMMIT();

#pragma unroll 1
    for (int kc = 0; kc < 4; kc++) {
        if (kc + 2 < 4) qk_issue(Ag, Bg, kc + 2, stg[(kc + 2) % 3], tid);
        CP_COMMIT();                    // real or empty group: keeps pending count fixed
        CP_WAIT2();
        __syncthreads();
        const uint32_t* As = stg[kc % 3];
        const uint32_t* Bs = As + 128 * QSTR;
#pragma unroll
        for (int ks = 0; ks < 4; ks++) {
            int k0 = ks * 8;
            uint32_t af[4][4], bf[4][2];
#pragma unroll
            for (int mt = 0; mt < 4; mt++) {
                int r0 = wm * 64 + mt * 16;
                af[mt][0] = As[(r0 + gq) * QSTR + k0 + c];
                af[mt][1] = As[(r0 + gq + 8) * QSTR + k0 + c];
                af[mt][2] = As[(r0 + gq) * QSTR + k0 + c + 4];
                af[mt][3] = As[(r0 + gq + 8) * QSTR + k0 + c + 4];
            }
#pragma unroll
            for (int nt = 0; nt < 4; nt++) {
                int n0 = wn * 32 + nt * 8;
                bf[nt][0] = Bs[(n0 + gq) * QSTR + k0 + c];
                bf[nt][1] = Bs[(n0 + gq) * QSTR + k0 + c + 4];
            }
#pragma unroll
            for (int mt = 0; mt < 4; mt++)
#pragma unroll
                for (int nt = 0; nt < 4; nt++)
                    mma_tf32(acc[mt][nt], af[mt], bf[nt]);
        }
        __syncthreads();
    }

    // Epilogue: exp (fp32) -> fp16 store + exact fp32 row-sum partials
    __half* outbase = g_scores + (size_t)pair * Ss * Ss;
#pragma unroll
    for (int mt = 0; mt < 4; mt++) {
        int rl = wm * 64 + mt * 16 + gq;
        float slo = 0.f, shi = 0.f;
#pragma unroll
        for (int nt = 0; nt < 4; nt++) {
            int colg = t0 + wn * 32 + nt * 8 + 2 * c;
            float e0 = __expf(acc[mt][nt][0] * SCALEF);
            float e1 = __expf(acc[mt][nt][1] * SCALEF);
            float e2 = __expf(acc[mt][nt][2] * SCALEF);
            float e3 = __expf(acc[mt][nt][3] * SCALEF);
            *(__half2*)(outbase + (size_t)(s0 + rl) * Ss + colg)     = __floats2half2_rn(e0, e1);
            *(__half2*)(outbase + (size_t)(s0 + rl + 8) * Ss + colg) = __floats2half2_rn(e2, e3);
            slo += e0 + e1; shi += e2 + e3;
        }
        slo += __shfl_xor_sync(0xFFFFFFFF, slo, 1);
        slo += __shfl_xor_sync(0xFFFFFFFF, slo, 2);
        shi += __shfl_xor_sync(0xFFFFFFFF, shi, 1);
        shi += __shfl_xor_sync(0xFFFFFFFF, shi, 2);
        if (c == 0) {
            atomicAdd(&ps[rl], slo);
            atomicAdd(&ps[rl + 8], shi);
        }
    }
    __syncthreads();
    if (tid < 128)
        g_psum[((size_t)pair * 8 + blockIdx.x) * Ss + s0 + tid] = ps[tid];
}

// ---------------- top-2 (ties -> lower index, matches jax top_k) ----------------
__device__ __forceinline__ void top2(const float* __restrict__ rp, int b, int& bi, int& si) {
    float best = -1e30f, second = -1e30f;
    bi = -1; si = -1;
#pragma unroll
    for (int e = 0; e < Ee; e++) {
        float v = rp[b * Ee + e];
        if (v > best)        { second = best; si = bi; best = v; bi = e; }
        else if (v > second) { second = v; si = e; }
    }
}

// ====================== Kernel 2: combine (fp16 in, fp16 out) + zero-fill out slices ======================
__global__ void __launch_bounds__(256) combine_kernel(const int* __restrict__ emask,
                                                      const float* __restrict__ rp,
                                                      float* __restrict__ outG) {
    int row = blockIdx.x;               // b*1024 + s
    int b = row >> 10, s = row & 1023;
    int tid = threadIdx.x;

    float4 a = make_float4(0.f, 0.f, 0.f, 0.f);
    for (int e = 0; e < Ee; e++) {
        int pair = e * Bb + b;
        if (emask[pair] == 0) continue;
        float sm = 0.f;
#pragma unroll
        for (int nt = 0; nt < 8; nt++)
            sm += g_psum[((size_t)pair * 8 + nt) * Ss + s];
        float inv = 1.0f / sm;
        uint2 raw = *(const uint2*)(g_scores + ((size_t)pair * Ss + s) * Ss + tid * 4);
        float2 f0 = __half22float2(*reinterpret_cast<__half2*>(&raw.x));
        float2 f1 = __half22float2(*reinterpret_cast<__half2*>(&raw.y));
        a.x += f0.x * inv; a.y += f0.y * inv;
        a.z += f1.x * inv; a.w += f1.y * inv;
    }
    uint2 o;
    __half2 h0 = __floats2half2_rn(a.x, a.y);
    __half2 h1 = __floats2half2_rn(a.z, a.w);
    o.x = *reinterpret_cast<uint32_t*>(&h0);
    o.y = *reinterpret_cast<uint32_t*>(&h1);
    *(uint2*)(g_attn + (size_t)row * Ss + tid * 4) = o;

    // zero the 6 non-selected 128-wide output slices of this (b, s) row
    int bi, si; top2(rp, b, bi, si);
    if (tid < 192) {
        int sl = tid >> 5;              // 0..5
        int cc = (tid & 31) << 2;       // float offset in slice
        int e, cnt = 0, eSel = -1;
#pragma unroll
        for (e = 0; e < Ee; e++) {
            if (e == bi || e == si) continue;
            if (cnt == sl) { eSel = e; }
            cnt++;
        }
        *(float4*)(outG + (size_t)row * Dd + eSel * DEe + cc) =
            make_float4(0.f, 0.f, 0.f, 0.f);
    }
}

// ====================== Kernel 3: transpose selected V slices (fp16 out) ======================
__global__ void __launch_bounds__(256) vt_prep(const float* __restrict__ V,
                                               const float* __restrict__ rp) {
    int tt = blockIdx.x;
    int se = blockIdx.y;
    int b  = blockIdx.z;
    int bi, si; top2(rp, b, bi, si);
    int eSel = (se == 0) ? bi : si;

    __shared__ float tile[64][132];
    int tid = threadIdx.x;
#pragma unroll
    for (int i = 0; i < 8; i++) {
        int v = tid + 256 * i;
        int r = v >> 5;
        int c = (v & 31) << 2;
        float4 val = *(const float4*)(V + ((size_t)(b * Ss + tt * 64 + r)) * Dd + eSel * DEe + c);
        *(float4*)&tile[r][c] = val;
    }
    __syncthreads();
#pragma unroll
    for (int i = 0; i < 8; i++) {
        int v = tid + 256 * i;
        int d = v >> 4;
        int t4 = (v & 15) << 2;
        uint2 o;
        __half2 h0 = __floats2half2_rn(tile[t4][d],     tile[t4 + 1][d]);
        __half2 h1 = __floats2half2_rn(tile[t4 + 2][d], tile[t4 + 3][d]);
        o.x = *reinterpret_cast<uint32_t*>(&h0);
        o.y = *reinterpret_cast<uint32_t*>(&h1);
        *(uint2*)(g_vt + ((size_t)((b * 2 + se) * DEe + d)) * Ss + tt * 64 + t4) = o;
    }
}

// ====================== Kernel 4: out = attn @ V — fp16 MMA, M=64, 3-stage, 2 CTAs/SM ======================
#define AK 64                 // k chunk (halfs)
#define ASTRH 72              // smem row stride in halfs (64 data + 8 pad)
#define ASTRW 36              // same, in 32-bit words
#define STAGE_H ((64 + 128) * ASTRH)       // halfs per stage
#define AV_SMEM (3 * STAGE_H * 2)          // bytes: 3 stages x 27648 B = 82944

__device__ __forceinline__ void av_issue(const __half* Ag, const __half* Bg, int kc,
                                         __half* stage, int tid) {
    __half* Abuf = stage;
    __half* Bbuf = stage + 64 * ASTRH;
#pragma unroll
    for (int i = 0; i < 2; i++) {       // A: 64 rows x 8 cp16 (8 halfs each) = 512 ops
        int idx = tid + 256 * i;
        int row = idx >> 3;
        int col = (idx & 7) << 3;       // half offset
        cp16(&Abuf[row * ASTRH + col], Ag + (size_t)row * Ss + kc * AK + col);
    }
#pragma unroll
    for (int i = 0; i < 4; i++) {       // B: 128 rows x 8 cp16 = 1024 ops
        int idx = tid + 256 * i;
        int row = idx >> 3;
        int col = (idx & 7) << 3;
        cp16(&Bbuf[row * ASTRH + col], Bg + (size_t)row * Ss + kc * AK + col);
    }
}

__global__ void __launch_bounds__(256) av_mma(const float* __restrict__ rp,
                                              float* __restrict__ outG) {
    int st = blockIdx.x;                // 0..15 (64 rows each)
    int se = blockIdx.y;                // 0..1 selected expert
    int b  = blockIdx.z;
    int tid = threadIdx.x;
    int wid = tid >> 5, lane = tid & 31;
    int s0 = st << 6;

    int bi, si; top2(rp, b, bi, si);
    int e = (se == 0) ? bi : si;

    extern __shared__ __half shh[];
    __half* stg[3] = { shh, shh + STAGE_H, shh + 2 * STAGE_H };

    int wm = wid & 1, wn = wid >> 1;    // 2 (m) x 4 (n)
    int gq = lane >> 2, c = lane & 3;

    const __half* Ag = g_attn + (size_t)(b * Ss + s0) * Ss;
    const __half* Bg = g_vt + (size_t)(b * 2 + se) * DEe * Ss;

    float acc[2][4][4] = {};

    av_issue(Ag, Bg, 0, stg[0], tid); CP_COMMIT();
    av_issue(Ag, Bg, 1, stg[1], tid); CP_COMMIT();

#pragma unroll 1
    for (int kc = 0; kc < 16; kc++) {
        if (kc + 2 < 16) av_issue(Ag, Bg, kc + 2, stg[(kc + 2) % 3], tid);
        CP_COMMIT();
        CP_WAIT2();
        __syncthreads();
        const uint32_t* As = (const uint32_t*)stg[kc % 3];
        const uint32_t* Bs = As + 64 * ASTRW;
#pragma unroll
        for (int ks = 0; ks < 4; ks++) {    // 4 x k16 = 64
            int k0 = ks * 8;                // word offset (16 halfs)
            uint32_t af[2][4], bf[4][2];
#pragma unroll
            for (int mt = 0; mt < 2; mt++) {
                int r0 = wm * 32 + mt * 16;
                af[mt][0] = As[(r0 + gq) * ASTRW + k0 + c];
                af[mt][1] = As[(r0 + gq + 8) * ASTRW + k0 + c];
                af[mt][2] = As[(r0 + gq) * ASTRW + k0 + c + 4];
                af[mt][3] = As[(r0 + gq + 8) * ASTRW + k0 + c + 4];
            }
#pragma unroll
            for (int nt = 0; nt < 4; nt++) {
                int n0 = wn * 32 + nt * 8;
                bf[nt][0] = Bs[(n0 + gq) * ASTRW + k0 + c];
                bf[nt][1] = Bs[(n0 + gq) * ASTRW + k0 + c + 4];
            }
#pragma unroll
            for (int mt = 0; mt < 2; mt++)
#pragma unroll
                for (int nt = 0; nt < 4; nt++)
                    mma_f16(acc[mt][nt], af[mt], bf[nt]);
        }
        __syncthreads();
    }

#pragma unroll
    for (int mt = 0; mt < 2; mt++) {
        int rl = wm * 32 + mt * 16 + gq;
#pragma unroll
        for (int nt = 0; nt < 4; nt++) {
            int colg = e * DEe + wn * 32 + nt * 8 + 2 * c;
            *(float2*)(outG + ((size_t)(b * Ss + s0 + rl)) * Dd + colg) =
                make_float2(acc[mt][nt][0], acc[mt][nt][1]);
            *(float2*)(outG + ((size_t)(b * Ss + s0 + rl + 8)) * Dd + colg) =
                make_float2(acc[mt][nt][2], acc[mt][nt][3]);
        }
    }
}

// ---------------- launch ----------------
extern "C" void kernel_launch(void* const* d_in, const int* in_sizes, int n_in,
                              void* d_out, int out_size) {
    const float* Q     = (const float*)d_in[0];
    const float* K     = (const float*)d_in[1];
    const float* V     = (const float*)d_in[2];
    const float* rp    = (const float*)d_in[3];
    const int*   emask = (const int*)  d_in[4];
    float* out = (float*)d_out;

    cudaFuncSetAttribute(qk_mma, cudaFuncAttributeMaxDynamicSharedMemorySize, QK_SMEM);
    cudaFuncSetAttribute(av_mma, cudaFuncAttributeMaxDynamicSharedMemorySize, AV_SMEM);

    vt_prep<<<dim3(16, 2, Bb), 256>>>(V, rp);
    qk_mma<<<dim3(8, 8, Ee * Bb), 256, QK_SMEM>>>(Q, K, emask);
    combine_kernel<<<Bb * Ss, 256>>>(emask, rp, out);
    av_mma<<<dim3(16, 2, Bb), 256, AV_SMEM>>>(rp, out);
}

// round 16
// speedup vs baseline: 1.3491x; 1.0843x over previous
#include <cuda_runtime.h>
#include <cuda_fp16.h>
#include <cstdint>
#include <math.h>

#define Bb 4
#define Ss 1024
#define Dd 1024
#define Ee 8
#define DEe 128
#define SCALEF 0.03125f

// ---------------- scratch ----------------
__device__ __half g_qh[(size_t)Bb * Ss * Dd];           // fp16 Q
__device__ __half g_kh[(size_t)Bb * Ss * Dd];           // fp16 K
__device__ __half g_scores[(size_t)Ee * Bb * Ss * Ss];  // exp(score*scale), fp16
__device__ float g_psum[(size_t)Ee * Bb * 8 * Ss];      // per (pair, t-tile) row sums (fp32)
__device__ __half g_attn[(size_t)Bb * Ss * Ss];         // fp16 normalized probs
__device__ __half g_vt[(size_t)Bb * 2 * DEe * Ss];      // fp16 transposed V [b][se][d][t]

__device__ __forceinline__ void mma_f16(float* d, const uint32_t* a, const uint32_t* b) {
    asm volatile(
        "mma.sync.aligned.m16n8k16.row.col.f32.f16.f16.f32 "
        "{%0,%1,%2,%3}, {%4,%5,%6,%7}, {%8,%9}, {%0,%1,%2,%3};"
        : "+f"(d[0]), "+f"(d[1]), "+f"(d[2]), "+f"(d[3])
        : "r"(a[0]), "r"(a[1]), "r"(a[2]), "r"(a[3]), "r"(b[0]), "r"(b[1]));
}

__device__ __forceinline__ void cp16(void* sdst, const void* gsrc) {
    uint32_t sa = (uint32_t)__cvta_generic_to_shared(sdst);
    asm volatile("cp.async.cg.shared.global [%0], [%1], 16;" :: "r"(sa), "l"(gsrc));
}
#define CP_COMMIT() asm volatile("cp.async.commit_group;" ::: "memory")
#define CP_WAIT0()  asm volatile("cp.async.wait_group 0;" ::: "memory")
#define CP_WAIT2()  asm volatile("cp.async.wait_group 2;" ::: "memory")

// ====================== Kernel 0: convert Q, K to fp16 ======================
__global__ void __launch_bounds__(256) qkh_prep(const float* __restrict__ Q,
                                                const float* __restrict__ K) {
    size_t t = (size_t)blockIdx.x * 256 + threadIdx.x;    // 524288 threads, 8 floats each
    size_t off = t * 8;
    float4 q0 = *(const float4*)(Q + off);
    float4 q1 = *(const float4*)(Q + off + 4);
    float4 k0 = *(const float4*)(K + off);
    float4 k1 = *(const float4*)(K + off + 4);
    uint4 oq, ok;
    __half2 h;
    h = __floats2half2_rn(q0.x, q0.y); oq.x = *(uint32_t*)&h;
    h = __floats2half2_rn(q0.z, q0.w); oq.y = *(uint32_t*)&h;
    h = __floats2half2_rn(q1.x, q1.y); oq.z = *(uint32_t*)&h;
    h = __floats2half2_rn(q1.z, q1.w); oq.w = *(uint32_t*)&h;
    h = __floats2half2_rn(k0.x, k0.y); ok.x = *(uint32_t*)&h;
    h = __floats2half2_rn(k0.z, k0.w); ok.y = *(uint32_t*)&h;
    h = __floats2half2_rn(k1.x, k1.y); ok.z = *(uint32_t*)&h;
    h = __floats2half2_rn(k1.z, k1.w); ok.w = *(uint32_t*)&h;
    *(uint4*)(g_qh + off) = oq;
    *(uint4*)(g_kh + off) = ok;
}

// ====================== Kernel 1: QK^T (fp16 MMA, single-shot tiles) + exp + psum ======================
#define QSTRH 136             // smem row stride in halfs (128 data + 8 pad)
#define QSTRW 68              // in words
#define QK_SMEM (2 * 128 * QSTRH * 2 + 512)   // A + B tiles + ps[128]

__global__ void __launch_bounds__(256) qk_mma(const int* __restrict__ emask) {
    int pair = blockIdx.z;              // e*4 + b
    if (emask[pair] == 0) return;
    int e = pair >> 2, b = pair & 3;
    int t0 = blockIdx.x << 7;
    int s0 = blockIdx.y << 7;

    extern __shared__ __half qsh[];
    __half* Ab = qsh;
    __half* Bb_ = qsh + 128 * QSTRH;
    float* ps = (float*)(qsh + 2 * 128 * QSTRH);

    int tid = threadIdx.x;
    int wid = tid >> 5, lane = tid & 31;
    int wm = wid & 1, wn = wid >> 1;    // warps: 2 (m) x 4 (n)
    int gq = lane >> 2, c = lane & 3;

    if (tid < 128) ps[tid] = 0.f;

    const __half* Ag = g_qh + (size_t)(b * Ss + s0) * Dd + e * DEe;
    const __half* Bg = g_kh + (size_t)(b * Ss + t0) * Dd + e * DEe;

    // single-shot load: A,B 128 rows x 128 halfs each (16 cp16 per row)
#pragma unroll
    for (int i = 0; i < 8; i++) {
        int idx = tid + 256 * i;
        int row = idx >> 4;
        int col = (idx & 15) << 3;
        cp16(&Ab[row * QSTRH + col], Ag + (size_t)row * Dd + col);
    }
#pragma unroll
    for (int i = 0; i < 8; i++) {
        int idx = tid + 256 * i;
        int row = idx >> 4;
        int col = (idx & 15) << 3;
        cp16(&Bb_[row * QSTRH + col], Bg + (size_t)row * Dd + col);
    }
    CP_COMMIT();
    CP_WAIT0();
    __syncthreads();

    const uint32_t* As = (const uint32_t*)Ab;
    const uint32_t* Bs = (const uint32_t*)Bb_;

    float acc[4][4][4] = {};
#pragma unroll
    for (int ks = 0; ks < 8; ks++) {    // 8 x k16 = 128
        int k0 = ks * 8;                // word offset
        uint32_t af[4][4], bf[4][2];
#pragma unroll
        for (int mt = 0; mt < 4; mt++) {
            int r0 = wm * 64 + mt * 16;
            af[mt][0] = As[(r0 + gq) * QSTRW + k0 + c];
            af[mt][1] = As[(r0 + gq + 8) * QSTRW + k0 + c];
            af[mt][2] = As[(r0 + gq) * QSTRW + k0 + c + 4];
            af[mt][3] = As[(r0 + gq + 8) * QSTRW + k0 + c + 4];
        }
#pragma unroll
        for (int nt = 0; nt < 4; nt++) {
            int n0 = wn * 32 + nt * 8;
            bf[nt][0] = Bs[(n0 + gq) * QSTRW + k0 + c];
            bf[nt][1] = Bs[(n0 + gq) * QSTRW + k0 + c + 4];
        }
#pragma unroll
        for (int mt = 0; mt < 4; mt++)
#pragma unroll
            for (int nt = 0; nt < 4; nt++)
                mma_f16(acc[mt][nt], af[mt], bf[nt]);
    }

    // Epilogue: exp (fp32) -> fp16 store + exact fp32 row-sum partials
    __half* outbase = g_scores + (size_t)pair * Ss * Ss;
#pragma unroll
    for (int mt = 0; mt < 4; mt++) {
        int rl = wm * 64 + mt * 16 + gq;
        float slo = 0.f, shi = 0.f;
#pragma unroll
        for (int nt = 0; nt < 4; nt++) {
            int colg = t0 + wn * 32 + nt * 8 + 2 * c;
            float e0 = __expf(acc[mt][nt][0] * SCALEF);
            float e1 = __expf(acc[mt][nt][1] * SCALEF);
            float e2 = __expf(acc[mt][nt][2] * SCALEF);
            float e3 = __expf(acc[mt][nt][3] * SCALEF);
            *(__half2*)(outbase + (size_t)(s0 + rl) * Ss + colg)     = __floats2half2_rn(e0, e1);
            *(__half2*)(outbase + (size_t)(s0 + rl + 8) * Ss + colg) = __floats2half2_rn(e2, e3);
            slo += e0 + e1; shi += e2 + e3;
        }
        slo += __shfl_xor_sync(0xFFFFFFFF, slo, 1);
        slo += __shfl_xor_sync(0xFFFFFFFF, slo, 2);
        shi += __shfl_xor_sync(0xFFFFFFFF, shi, 1);
        shi += __shfl_xor_sync(0xFFFFFFFF, shi, 2);
        if (c == 0) {
            atomicAdd(&ps[rl], slo);
            atomicAdd(&ps[rl + 8], shi);
        }
    }
    __syncthreads();
    if (tid < 128)
        g_psum[((size_t)pair * 8 + blockIdx.x) * Ss + s0 + tid] = ps[tid];
}

// ---------------- top-2 (ties -> lower index, matches jax top_k) ----------------
__device__ __forceinline__ void top2(const float* __restrict__ rp, int b, int& bi, int& si) {
    float best = -1e30f, second = -1e30f;
    bi = -1; si = -1;
#pragma unroll
    for (int e = 0; e < Ee; e++) {
        float v = rp[b * Ee + e];
        if (v > best)        { second = best; si = bi; best = v; bi = e; }
        else if (v > second) { second = v; si = e; }
    }
}

// ====================== Kernel 2: combine (fp16 in, fp16 out) + zero-fill out slices ======================
__global__ void __launch_bounds__(256) combine_kernel(const int* __restrict__ emask,
                                                      const float* __restrict__ rp,
                                                      float* __restrict__ outG) {
    int row = blockIdx.x;               // b*1024 + s
    int b = row >> 10, s = row & 1023;
    int tid = threadIdx.x;

    float4 a = make_float4(0.f, 0.f, 0.f, 0.f);
    for (int e = 0; e < Ee; e++) {
        int pair = e * Bb + b;
        if (emask[pair] == 0) continue;
        float sm = 0.f;
#pragma unroll
        for (int nt = 0; nt < 8; nt++)
            sm += g_psum[((size_t)pair * 8 + nt) * Ss + s];
        float inv = 1.0f / sm;
        uint2 raw = *(const uint2*)(g_scores + ((size_t)pair * Ss + s) * Ss + tid * 4);
        float2 f0 = __half22float2(*reinterpret_cast<__half2*>(&raw.x));
        float2 f1 = __half22float2(*reinterpret_cast<__half2*>(&raw.y));
        a.x += f0.x * inv; a.y += f0.y * inv;
        a.z += f1.x * inv; a.w += f1.y * inv;
    }
    uint2 o;
    __half2 h0 = __floats2half2_rn(a.x, a.y);
    __half2 h1 = __floats2half2_rn(a.z, a.w);
    o.x = *reinterpret_cast<uint32_t*>(&h0);
    o.y = *reinterpret_cast<uint32_t*>(&h1);
    *(uint2*)(g_attn + (size_t)row * Ss + tid * 4) = o;

    // zero the 6 non-selected 128-wide output slices of this (b, s) row
    int bi, si; top2(rp, b, bi, si);
    if (tid < 192) {
        int sl = tid >> 5;              // 0..5
        int cc = (tid & 31) << 2;       // float offset in slice
        int e, cnt = 0, eSel = -1;
#pragma unroll
        for (e = 0; e < Ee; e++) {
            if (e == bi || e == si) continue;
            if (cnt == sl) { eSel = e; }
            cnt++;
        }
        *(float4*)(outG + (size_t)row * Dd + eSel * DEe + cc) =
            make_float4(0.f, 0.f, 0.f, 0.f);
    }
}

// ====================== Kernel 3: transpose selected V slices (fp16 out) ======================
__global__ void __launch_bounds__(256) vt_prep(const float* __restrict__ V,
                                               const float* __restrict__ rp) {
    int tt = blockIdx.x;
    int se = blockIdx.y;
    int b  = blockIdx.z;
    int bi, si; top2(rp, b, bi, si);
    int eSel = (se == 0) ? bi : si;

    __shared__ float tile[64][132];
    int tid = threadIdx.x;
#pragma unroll
    for (int i = 0; i < 8; i++) {
        int v = tid + 256 * i;
        int r = v >> 5;
        int c = (v & 31) << 2;
        float4 val = *(const float4*)(V + ((size_t)(b * Ss + tt * 64 + r)) * Dd + eSel * DEe + c);
        *(float4*)&tile[r][c] = val;
    }
    __syncthreads();
#pragma unroll
    for (int i = 0; i < 8; i++) {
        int v = tid + 256 * i;
        int d = v >> 4;
        int t4 = (v & 15) << 2;
        uint2 o;
        __half2 h0 = __floats2half2_rn(tile[t4][d],     tile[t4 + 1][d]);
        __half2 h1 = __floats2half2_rn(tile[t4 + 2][d], tile[t4 + 3][d]);
        o.x = *reinterpret_cast<uint32_t*>(&h0);
        o.y = *reinterpret_cast<uint32_t*>(&h1);
        *(uint2*)(g_vt + ((size_t)((b * 2 + se) * DEe + d)) * Ss + tt * 64 + t4) = o;
    }
}

// ====================== Kernel 4: out = attn @ V — fp16 MMA, M=64, 3-stage ======================
#define AK 64                 // k chunk (halfs)
#define ASTRH 72              // smem row stride in halfs
#define ASTRW 36
#define STAGE_H ((64 + 128) * ASTRH)
#define AV_SMEM (3 * STAGE_H * 2)

__device__ __forceinline__ void av_issue(const __half* Ag, const __half* Bg, int kc,
                                         __half* stage, int tid) {
    __half* Abuf = stage;
    __half* Bbuf = stage + 64 * ASTRH;
#pragma unroll
    for (int i = 0; i < 2; i++) {       // A: 64 rows x 8 cp16
        int idx = tid + 256 * i;
        int row = idx >> 3;
        int col = (idx & 7) << 3;
        cp16(&Abuf[row * ASTRH + col], Ag + (size_t)row * Ss + kc * AK + col);
    }
#pragma unroll
    for (int i = 0; i < 4; i++) {       // B: 128 rows x 8 cp16
        int idx = tid + 256 * i;
        int row = idx >> 3;
        int col = (idx & 7) << 3;
        cp16(&Bbuf[row * ASTRH + col], Bg + (size_t)row * Ss + kc * AK + col);
    }
}

__global__ void __launch_bounds__(256) av_mma(const float* __restrict__ rp,
                                              float* __restrict__ outG) {
    int st = blockIdx.x;                // 0..15 (64 rows each)
    int se = blockIdx.y;                // 0..1 selected expert
    int b  = blockIdx.z;
    int tid = threadIdx.x;
    int wid = tid >> 5, lane = tid & 31;
    int s0 = st << 6;

    int bi, si; top2(rp, b, bi, si);
    int e = (se == 0) ? bi : si;

    extern __shared__ __half shh[];
    __half* stg[3] = { shh, shh + STAGE_H, shh + 2 * STAGE_H };

    int wm = wid & 1, wn = wid >> 1;    // 2 (m) x 4 (n)
    int gq = lane >> 2, c = lane & 3;

    const __half* Ag = g_attn + (size_t)(b * Ss + s0) * Ss;
    const __half* Bg = g_vt + (size_t)(b * 2 + se) * DEe * Ss;

    float acc[2][4][4] = {};

    av_issue(Ag, Bg, 0, stg[0], tid); CP_COMMIT();
    av_issue(Ag, Bg, 1, stg[1], tid); CP_COMMIT();

#pragma unroll 1
    for (int kc = 0; kc < 16; kc++) {
        if (kc + 2 < 16) av_issue(Ag, Bg, kc + 2, stg[(kc + 2) % 3], tid);
        CP_COMMIT();
        CP_WAIT2();
        __syncthreads();
        const uint32_t* As = (const uint32_t*)stg[kc % 3];
        const uint32_t* Bs = As + 64 * ASTRW;
#pragma unroll
        for (int ks = 0; ks < 4; ks++) {    // 4 x k16 = 64
            int k0 = ks * 8;
            uint32_t af[2][4], bf[4][2];
#pragma unroll
            for (int mt = 0; mt < 2; mt++) {
                int r0 = wm * 32 + mt * 16;
                af[mt][0] = As[(r0 + gq) * ASTRW + k0 + c];
                af[mt][1] = As[(r0 + gq + 8) * ASTRW + k0 + c];
                af[mt][2] = As[(r0 + gq) * ASTRW + k0 + c + 4];
                af[mt][3] = As[(r0 + gq + 8) * ASTRW + k0 + c + 4];
            }
#pragma unroll
            for (int nt = 0; nt < 4; nt++) {
                int n0 = wn * 32 + nt * 8;
                bf[nt][0] = Bs[(n0 + gq) * ASTRW + k0 + c];
                bf[nt][1] = Bs[(n0 + gq) * ASTRW + k0 + c + 4];
            }
#pragma unroll
            for (int mt = 0; mt < 2; mt++)
#pragma unroll
                for (int nt = 0; nt < 4; nt++)
                    mma_f16(acc[mt][nt], af[mt], bf[nt]);
        }
        __syncthreads();
    }

#pragma unroll
    for (int mt = 0; mt < 2; mt++) {
        int rl = wm * 32 + mt * 16 + gq;
#pragma unroll
        for (int nt = 0; nt < 4; nt++) {
            int colg = e * DEe + wn * 32 + nt * 8 + 2 * c;
            *(float2*)(outG + ((size_t)(b * Ss + s0 + rl)) * Dd + colg) =
                make_float2(acc[mt][nt][0], acc[mt][nt][1]);
            *(float2*)(outG + ((size_t)(b * Ss + s0 + rl + 8)) * Dd + colg) =
                make_float2(acc[mt][nt][2], acc[mt][nt][3]);
        }
    }
}

// ---------------- launch ----------------
extern "C" void kernel_launch(void* const* d_in, const int* in_sizes, int n_in,
                              void* d_out, int out_size) {
    const float* Q     = (const float*)d_in[0];
    const float* K     = (const float*)d_in[1];
    const float* V     = (const float*)d_in[2];
    const float* rp    = (const float*)d_in[3];
    const int*   emask = (const int*)  d_in[4];
    float* out = (float*)d_out;

    cudaFuncSetAttribute(qk_mma, cudaFuncAttributeMaxDynamicSharedMemorySize, QK_SMEM);
    cudaFuncSetAttribute(av_mma, cudaFuncAttributeMaxDynamicSharedMemorySize, AV_SMEM);

    qkh_prep<<<2048, 256>>>(Q, K);
    vt_prep<<<dim3(16, 2, Bb), 256>>>(V, rp);
    qk_mma<<<dim3(8, 8, Ee * Bb), 256, QK_SMEM>>>(emask);
    combine_kernel<<<Bb * Ss, 256>>>(emask, rp, out);
    av_mma<<<dim3(16, 2, Bb), 256, AV_SMEM>>>(rp, out);
}